// round 14
// baseline (speedup 1.0000x reference)
#include <cuda_runtime.h>
#include <cuda_bf16.h>
#include <cstdint>

#define GENE   2000
#define TE     128
#define HID    2048
#define KIN    2128      // GENE + TE (time embedding lives in x tail)
#define NSTEP  256
#define GRID   128
#define BLOCK  1024      // 32 warps/SM: latency hiding (occ was 25%, issue 24.5%)
#define NCOL   16        // output columns per CTA
#define DT     (1.0f/255.0f)
#define CHUNK  512
#define NBUF   5
#define LOOKAHEAD 4                         // chunks in flight; wait_group 3
#define BUF_BYTES (CHUNK*NCOL*2)            // 16 KB (bf16)
#define XS_FLOATS 2176
#define SLAB_BYTES (HID*NCOL*2)             // 64 KB resident slab per layer
#define SMEM_BYTES (XS_FLOATS*4 + NBUF*BUF_BYTES + 2*SLAB_BYTES)   // 216.5 KB

// Permuted bf16 weights: per-CTA slice contiguous.
#define OFF0   0L
#define OFF1   (OFF0 + 128L*KIN*NCOL)
#define OFF2   (OFF1 + 128L*HID*NCOL)
#define OFF3   (OFF2 + 128L*HID*NCOL)
#define OFF4   (OFF3 + 128L*HID*NCOL)
#define OFFO   (OFF4 + 128L*HID*NCOL)
#define TOTALF (OFFO + 125L*HID*NCOL)       // ~25.2M bf16 = ~48 MB

// Persistent scratch (device globals: allocation is forbidden)
__device__ __nv_bfloat16 g_wrep[TOTALF];
__device__ float    g_x[2][2176];      // x ping-pong: [0,2000)=x, [2000,2128)=te(t)
__device__ float    g_h0[HID];
__device__ float    g_h1[HID];
__device__ float    g_te[NSTEP][TE];
__device__ unsigned g_count;           // flat barrier counter (red-based)

// ---------------------------------------------------------------------------
// Grid barrier: FLAT monotonic counter (red.release arrival, acquire poll).
// ---------------------------------------------------------------------------
__device__ __forceinline__ void grid_barrier(unsigned& nbar) {
    __syncthreads();
    ++nbar;
    if (threadIdx.x == 0) {
        asm volatile("red.release.gpu.add.u32 [%0], 1;" :: "l"(&g_count) : "memory");
        const unsigned target = nbar * GRID;
        unsigned cur;
        do {
            asm volatile("ld.acquire.gpu.u32 %0, [%1];" : "=r"(cur) : "l"(&g_count) : "memory");
        } while (cur < target);
    }
    __syncthreads();
}

// ---------------------------------------------------------------------------
// cp.async helpers (.cg; DRAM=0.1% measured, weights are L2-resident).
// ---------------------------------------------------------------------------
__device__ __forceinline__ void cp16(char* dst, const char* src) {
    unsigned a = (unsigned)__cvta_generic_to_shared(dst);
    asm volatile("cp.async.cg.shared.global [%0], [%1], 16;" :: "r"(a), "l"(src));
}

// One CHUNK-row slab (bf16, contiguous) -> smem buf. One commit, all threads.
__device__ __forceinline__ void prefetch_chunk(const char* __restrict__ slice,
        int K, int base, char* __restrict__ buf, int tid, bool active) {
    if (active) {
        const int lim = K * 2;            // 16B segments in whole slice
        const int s   = base * 2 + tid;   // 1 segment per thread
        if (s < lim && tid < CHUNK*2)
            cp16(buf + tid*16, slice + (long)s*16);
    }
    asm volatile("cp.async.commit_group;");
}

// 8-col MAC on one 32-byte weight row (jv selects the 16B half).
__device__ __forceinline__ void mac8(float* acc, const char* rowp, int jv, float xv) {
    const uint4 wv = *reinterpret_cast<const uint4*>(rowp + jv*16);
    const float2 f0 = __bfloat1622float2(*reinterpret_cast<const __nv_bfloat162*>(&wv.x));
    const float2 f1 = __bfloat1622float2(*reinterpret_cast<const __nv_bfloat162*>(&wv.y));
    const float2 f2 = __bfloat1622float2(*reinterpret_cast<const __nv_bfloat162*>(&wv.z));
    const float2 f3 = __bfloat1622float2(*reinterpret_cast<const __nv_bfloat162*>(&wv.w));
    acc[0] = fmaf(xv, f0.x, acc[0]);
    acc[1] = fmaf(xv, f0.y, acc[1]);
    acc[2] = fmaf(xv, f1.x, acc[2]);
    acc[3] = fmaf(xv, f1.y, acc[3]);
    acc[4] = fmaf(xv, f2.x, acc[4]);
    acc[5] = fmaf(xv, f2.y, acc[5]);
    acc[6] = fmaf(xv, f3.x, acc[6]);
    acc[7] = fmaf(xv, f3.y, acc[7]);
}

// Cross-thread reduction of 8-col accumulators over 32 warps. Returns the
// column sum for tid<16 (col j0+tid).
__device__ __forceinline__ float reduce_tail(float* acc, float (*red2)[2][8], int tid) {
    #pragma unroll
    for (int m = 2; m <= 16; m <<= 1) {
        #pragma unroll
        for (int k = 0; k < 8; ++k)
            acc[k] += __shfl_xor_sync(0xffffffffu, acc[k], m);
    }
    const int warp = tid >> 5;
    const int lane = tid & 31;
    if (lane < 2) {
        #pragma unroll
        for (int k = 0; k < 8; ++k) red2[warp][lane][k] = acc[k];
    }
    __syncthreads();
    float r = 0.f;
    if (tid < NCOL) {
        const int cj = tid >> 3;
        const int ck = tid & 7;
        float a0 = 0.f, a1 = 0.f, a2 = 0.f, a3 = 0.f;
        #pragma unroll
        for (int w = 0; w < 32; w += 4) {
            a0 += red2[w+0][cj][ck];
            a1 += red2[w+1][cj][ck];
            a2 += red2[w+2][cj][ck];
            a3 += red2[w+3][cj][ck];
        }
        r = (a0 + a1) + (a2 + a3);
    }
    return r;
}

// ---------------------------------------------------------------------------
// Streamed layer: chunks 0..3 in flight on entry; issues its remaining
// chunks then next STREAMED layer's chunks 0..3. Result valid for tid<16.
// ---------------------------------------------------------------------------
__device__ __forceinline__ float stream_layer(
    const char* __restrict__ slice,  int K,  bool act,
    const char* __restrict__ slicen, int Kn, bool actn,
    const float* __restrict__ in,
    float* __restrict__ xs, char* __restrict__ bufs,
    int& is, int& rs, float (*red2)[2][8],
    int tid, unsigned& nbar)
{
    grid_barrier(nbar);

    const int K4 = K >> 2;
    for (int i = tid; i < K4; i += BLOCK)
        reinterpret_cast<float4*>(xs)[i] =
            __ldcg(reinterpret_cast<const float4*>(in) + i);

    const int kw = tid >> 1;          // row within chunk (0..511)
    const int jv = tid & 1;
    float acc[8];
    #pragma unroll
    for (int k = 0; k < 8; ++k) acc[k] = 0.f;

    const int nc = (K + CHUNK - 1) / CHUNK;
    for (int c = 0; c < nc; ++c) {
        asm volatile("cp.async.wait_group 3;");   // chunk c landed
        __syncthreads();                          // ..and chunk c-1 reads done

        if (c < nc - LOOKAHEAD)
            prefetch_chunk(slice,  K,  (c + LOOKAHEAD)*CHUNK,
                           bufs + is*BUF_BYTES, tid, act);
        else
            prefetch_chunk(slicen, Kn, (c - (nc - LOOKAHEAD))*CHUNK,
                           bufs + is*BUF_BYTES, tid, actn);
        if (++is == NBUF) is = 0;

        if (act) {
            const char* __restrict__ buf = bufs + rs*BUF_BYTES;
            const int base = c * CHUNK;
            const int rows = min(CHUNK, K - base);
            if (kw < rows)                        // 1 row per thread per chunk
                mac8(acc, buf + kw*32, jv, xs[base + kw]);
        }
        if (++rs == NBUF) rs = 0;
    }
    return reduce_tail(acc, red2, tid);
}

// ---------------------------------------------------------------------------
// Resident layer: weights live permanently in SMEM. No chunk machinery.
// ---------------------------------------------------------------------------
__device__ __forceinline__ float resident_layer(
    const char* __restrict__ wres,
    const float* __restrict__ in,
    float* __restrict__ xs, float (*red2)[2][8],
    int tid, unsigned& nbar)
{
    grid_barrier(nbar);

    for (int i = tid; i < HID/4; i += BLOCK)
        reinterpret_cast<float4*>(xs)[i] =
            __ldcg(reinterpret_cast<const float4*>(in) + i);
    __syncthreads();

    const int kw = tid >> 1;
    const int jv = tid & 1;
    float acc[8];
    #pragma unroll
    for (int k = 0; k < 8; ++k) acc[k] = 0.f;

    #pragma unroll
    for (int i = 0; i < HID/(BLOCK/2); ++i) {     // 4 iters
        const int r = kw + i*(BLOCK/2);
        mac8(acc, wres + r*32, jv, xs[r]);
    }
    return reduce_tail(acc, red2, tid);
}

__device__ __forceinline__ void store_hidden(float r,
        const float* __restrict__ bias, float* __restrict__ out,
        int j0, int tid)
{
    if (tid < NCOL) {
        const int j = j0 + tid;
        out[j] = fmaxf(r + __ldg(bias + j), 0.f);
    }
}

// ---------------------------------------------------------------------------
// Setup kernel: weight reorg (y = 0..5) + barrier/x0/te init (y = 6), fused
// so the bridge kernel is the 2nd launch per replay (ncu sampling hits it).
// ---------------------------------------------------------------------------
__global__ void setup_kernel(
    const float* __restrict__ w0, const float* __restrict__ w1,
    const float* __restrict__ w2, const float* __restrict__ w3,
    const float* __restrict__ w4, const float* __restrict__ wout,
    const float* __restrict__ start,
    const float* __restrict__ te_w1, const float* __restrict__ te_b1,
    const float* __restrict__ te_w2, const float* __restrict__ te_b2,
    float* __restrict__ out)
{
    const int b = blockIdx.x;   // 0..127
    const int l = blockIdx.y;   // 0..6

    if (l < 6) {                // ---- weight reorg ----
        const float* W; int K, O; long off;
        switch (l) {
            case 0: W = w0;   K = KIN; O = HID;  off = OFF0; break;
            case 1: W = w1;   K = HID; O = HID;  off = OFF1; break;
            case 2: W = w2;   K = HID; O = HID;  off = OFF2; break;
            case 3: W = w3;   K = HID; O = HID;  off = OFF3; break;
            case 4: W = w4;   K = HID; O = HID;  off = OFF4; break;
            default:W = wout; K = HID; O = GENE; off = OFFO; break;
        }
        const int j0 = b * NCOL;
        if (j0 >= O) return;
        __nv_bfloat16* dst = g_wrep + off + (long)b * K * NCOL;
        const int n4 = K * (NCOL/4);
        for (int e = threadIdx.x; e < n4; e += blockDim.x) {
            const int r  = e >> 2;
            const int c4 = (e & 3) * 4;
            const float4 w = *reinterpret_cast<const float4*>(W + (long)r * O + j0 + c4);
            uint2 p;
            __nv_bfloat162 p0 = __float22bfloat162_rn(make_float2(w.x, w.y));
            __nv_bfloat162 p1 = __float22bfloat162_rn(make_float2(w.z, w.w));
            p.x = *reinterpret_cast<unsigned*>(&p0);
            p.y = *reinterpret_cast<unsigned*>(&p1);
            *reinterpret_cast<uint2*>(dst + (long)e * 4) = p;
        }
    } else {                    // ---- init: t = 2b and 2b+1 ----
        __shared__ float h[2][TE];
        const int half = threadIdx.x >> 7;       // 0 or 1
        const int lane = threadIdx.x & 127;
        const int t    = 2*b + half;
        const float tt = (float)t * DT;
        h[half][lane] = fmaxf(fmaf(tt, te_w1[lane], te_b1[lane]), 0.f);
        __syncthreads();
        float acc = te_b2[lane];
        #pragma unroll 8
        for (int k = 0; k < TE; ++k)
            acc = fmaf(h[half][k], te_w2[k * TE + lane], acc);
        if (t >= 1) {
            g_te[t][lane] = acc;
            if (t == 1) g_x[0][GENE + lane] = acc;   // te(1) tail for step 1
        } else {                // t == 0: barrier reset + x0 seed + row 0
            if (lane == 0) g_count = 0u;
            for (int k = lane; k < GENE; k += TE) {
                const float v = start[k];
                g_x[0][k] = v;
                out[k]    = v;
            }
        }
    }
}

// ---------------------------------------------------------------------------
// Persistent kernel: 255 Euler steps, 6 flat barriers/step, 32 warps/SM.
// Layers 1-2 from SMEM-resident slabs; layers 0,3,4,out stream via depth-5
// cp.async with 4-chunk cross-layer lookahead.
// ---------------------------------------------------------------------------
__global__ void __launch_bounds__(BLOCK, 1) bridge_kernel(
    const float* __restrict__ b0, const float* __restrict__ b1,
    const float* __restrict__ b2, const float* __restrict__ b3,
    const float* __restrict__ b4, const float* __restrict__ bout,
    float* __restrict__ out)
{
    extern __shared__ float smem[];
    float* xs   = smem;                                 // 2176 floats
    char*  bufs = reinterpret_cast<char*>(smem + XS_FLOATS);
    char*  rw1  = bufs + NBUF*BUF_BYTES;                // resident w1 slab
    char*  rw2  = rw1 + SLAB_BYTES;                     // resident w2 slab
    __shared__ float red2[32][2][8];

    const int tid = threadIdx.x;
    const int b   = blockIdx.x;
    const int j0  = b * NCOL;
    const bool actO = (j0 < GENE);      // active in the output layer

    const char* s0 = reinterpret_cast<const char*>(g_wrep + OFF0 + (long)b * KIN * NCOL);
    const char* s1 = reinterpret_cast<const char*>(g_wrep + OFF1 + (long)b * HID * NCOL);
    const char* s2 = reinterpret_cast<const char*>(g_wrep + OFF2 + (long)b * HID * NCOL);
    const char* s3 = reinterpret_cast<const char*>(g_wrep + OFF3 + (long)b * HID * NCOL);
    const char* s4 = reinterpret_cast<const char*>(g_wrep + OFF4 + (long)b * HID * NCOL);
    const char* so = reinterpret_cast<const char*>(g_wrep + OFFO + (long)b * HID * NCOL);

    unsigned nbar = 0;
    int is = 0, rs = 0;

    // Prologue: resident slabs (one cp.async group, drains at first wait),
    // then chunks 0..3 of step-1 layer0.
    for (int i = tid; i < SLAB_BYTES/16; i += BLOCK) cp16(rw1 + i*16, s1 + (long)i*16);
    for (int i = tid; i < SLAB_BYTES/16; i += BLOCK) cp16(rw2 + i*16, s2 + (long)i*16);
    asm volatile("cp.async.commit_group;");
    #pragma unroll
    for (int c = 0; c < LOOKAHEAD; ++c)
        prefetch_chunk(s0, KIN, c*CHUNK, bufs + c*BUF_BYTES, tid, true);
    is = LOOKAHEAD;

    for (int t = 1; t < NSTEP; ++t) {
        const float* xprev = g_x[(t - 1) & 1];
        float*       xcur  = g_x[t & 1];
        float r;

        r = stream_layer(s0, KIN, true,  s3, HID, true,  xprev,
                         xs, bufs, is, rs, red2, tid, nbar);
        store_hidden(r, b0, g_h0, j0, tid);

        r = resident_layer(rw1, g_h0, xs, red2, tid, nbar);
        store_hidden(r, b1, g_h1, j0, tid);

        r = resident_layer(rw2, g_h1, xs, red2, tid, nbar);
        store_hidden(r, b2, g_h0, j0, tid);

        r = stream_layer(s3, HID, true,  s4, HID, true,  g_h0,
                         xs, bufs, is, rs, red2, tid, nbar);
        store_hidden(r, b3, g_h1, j0, tid);

        r = stream_layer(s4, HID, true,  so, HID, actO,  g_h1,
                         xs, bufs, is, rs, red2, tid, nbar);
        store_hidden(r, b4, g_h0, j0, tid);

        // Final layer + Euler update + trajectory store
        r = stream_layer(so, HID, actO,  s0, KIN, true,  g_h0,
                         xs, bufs, is, rs, red2, tid, nbar);
        if (tid < NCOL && actO) {
            const int j = j0 + tid;
            const float xn = fmaf(r + __ldg(bout + j), DT, __ldcg(xprev + j));
            xcur[j] = xn;
            __stcs(out + (size_t)t * GENE + j, xn);
        }
        // tail CTA installs te(t+1) into xcur tail for next step's layer0
        if (b == GRID - 1 && t + 1 < NSTEP && tid < TE)
            xcur[GENE + tid] = g_te[t + 1][tid];
    }
}

extern "C" void kernel_launch(void* const* d_in, const int* in_sizes, int n_in,
                              void* d_out, int out_size)
{
    (void)in_sizes; (void)n_in; (void)out_size;
    const float* start  = (const float*)d_in[0];
    // d_in[1] = end_state (unused)
    const float* te_w1  = (const float*)d_in[2];
    const float* te_b1  = (const float*)d_in[3];
    const float* te_w2  = (const float*)d_in[4];
    const float* te_b2  = (const float*)d_in[5];
    const float* w0     = (const float*)d_in[6];
    const float* b0     = (const float*)d_in[7];
    const float* w1     = (const float*)d_in[8];
    const float* b1     = (const float*)d_in[9];
    const float* w2     = (const float*)d_in[10];
    const float* b2     = (const float*)d_in[11];
    const float* w3     = (const float*)d_in[12];
    const float* b3     = (const float*)d_in[13];
    const float* w4     = (const float*)d_in[14];
    const float* b4     = (const float*)d_in[15];
    const float* wout   = (const float*)d_in[16];
    const float* bout   = (const float*)d_in[17];
    float* out = (float*)d_out;

    cudaFuncSetAttribute(bridge_kernel,
                         cudaFuncAttributeMaxDynamicSharedMemorySize, SMEM_BYTES);

    dim3 sg(GRID, 7);
    setup_kernel<<<sg, 256>>>(w0, w1, w2, w3, w4, wout,
                              start, te_w1, te_b1, te_w2, te_b2, out);
    bridge_kernel<<<GRID, BLOCK, SMEM_BYTES>>>(b0, b1, b2, b3, b4, bout, out);
}

// round 15
// speedup vs baseline: 1.1732x; 1.1732x over previous
#include <cuda_runtime.h>
#include <cuda_bf16.h>
#include <cstdint>

#define GENE   2000
#define TE     128
#define HID    2048
#define KIN    2128      // GENE + TE (time embedding lives in x tail)
#define NSTEP  256
#define GRID   128
#define BLOCK  512
#define NCOL   16        // output columns per CTA
#define DT     (1.0f/255.0f)
#define CHUNK  512
#define NBUF   5
#define LOOKAHEAD 4                         // chunks in flight; wait_group 3
#define BUF_BYTES (CHUNK*NCOL*2)            // 16 KB (bf16)
#define SLAB_BYTES (HID*NCOL*2)             // 64 KB resident slab per layer
#define SMEM_BYTES (NBUF*BUF_BYTES + 2*SLAB_BYTES)   // 208 KB (no xs staging)

// Permuted bf16 weights: per-CTA slice contiguous.
#define OFF0   0L
#define OFF1   (OFF0 + 128L*KIN*NCOL)
#define OFF2   (OFF1 + 128L*HID*NCOL)
#define OFF3   (OFF2 + 128L*HID*NCOL)
#define OFF4   (OFF3 + 128L*HID*NCOL)
#define OFFO   (OFF4 + 128L*HID*NCOL)
#define TOTALF (OFFO + 125L*HID*NCOL)       // ~25.2M bf16 = ~48 MB

// Persistent scratch (device globals: allocation is forbidden)
__device__ __nv_bfloat16 g_wrep[TOTALF];
__device__ float    g_x[2][2176];      // x ping-pong: [0,2000)=x, [2000,2128)=te(t)
__device__ float    g_h0[HID];
__device__ float    g_h1[HID];
__device__ float    g_te[NSTEP][TE];
__device__ unsigned g_count;           // flat barrier counter (red-based)

// ---------------------------------------------------------------------------
// Grid barrier: FLAT monotonic counter (red.release arrival, acquire poll).
// ---------------------------------------------------------------------------
__device__ __forceinline__ void grid_barrier(unsigned& nbar) {
    __syncthreads();
    ++nbar;
    if (threadIdx.x == 0) {
        asm volatile("red.release.gpu.add.u32 [%0], 1;" :: "l"(&g_count) : "memory");
        const unsigned target = nbar * GRID;
        unsigned cur;
        do {
            asm volatile("ld.acquire.gpu.u32 %0, [%1];" : "=r"(cur) : "l"(&g_count) : "memory");
        } while (cur < target);
    }
    __syncthreads();
}

// ---------------------------------------------------------------------------
// cp.async helpers (.cg; measured DRAM=0.1%, weights are L2-resident).
// ---------------------------------------------------------------------------
__device__ __forceinline__ void cp16(char* dst, const char* src) {
    unsigned a = (unsigned)__cvta_generic_to_shared(dst);
    asm volatile("cp.async.cg.shared.global [%0], [%1], 16;" :: "r"(a), "l"(src));
}

// One CHUNK-row slab (bf16, contiguous) -> smem buf. One commit, all threads.
__device__ __forceinline__ void prefetch_chunk(const char* __restrict__ slice,
        int K, int base, char* __restrict__ buf, int tid, bool active) {
    if (active) {
        const int lim = K * 2;            // 16B segments in whole slice
        const int s0  = base * 2;
        #pragma unroll
        for (int i = 0; i < (CHUNK*2)/BLOCK; ++i) {   // 2 segs/thread
            const int s = tid + i*BLOCK;
            if (s0 + s < lim)
                cp16(buf + s*16, slice + (long)(s0 + s)*16);
        }
    }
    asm volatile("cp.async.commit_group;");
}

// 8-col MAC on one 32-byte weight row (jv selects the 16B half).
__device__ __forceinline__ void mac8(float* acc, const char* rowp, int jv, float xv) {
    const uint4 wv = *reinterpret_cast<const uint4*>(rowp + jv*16);
    const float2 f0 = __bfloat1622float2(*reinterpret_cast<const __nv_bfloat162*>(&wv.x));
    const float2 f1 = __bfloat1622float2(*reinterpret_cast<const __nv_bfloat162*>(&wv.y));
    const float2 f2 = __bfloat1622float2(*reinterpret_cast<const __nv_bfloat162*>(&wv.z));
    const float2 f3 = __bfloat1622float2(*reinterpret_cast<const __nv_bfloat162*>(&wv.w));
    acc[0] = fmaf(xv, f0.x, acc[0]);
    acc[1] = fmaf(xv, f0.y, acc[1]);
    acc[2] = fmaf(xv, f1.x, acc[2]);
    acc[3] = fmaf(xv, f1.y, acc[3]);
    acc[4] = fmaf(xv, f2.x, acc[4]);
    acc[5] = fmaf(xv, f2.y, acc[5]);
    acc[6] = fmaf(xv, f3.x, acc[6]);
    acc[7] = fmaf(xv, f3.y, acc[7]);
}

// Cross-thread reduction of 8-col accumulators over 16 warps. Returns the
// column sum for tid<16 (col j0+tid).
__device__ __forceinline__ float reduce_tail(float* acc, float (*red2)[2][8], int tid) {
    #pragma unroll
    for (int m = 2; m <= 16; m <<= 1) {
        #pragma unroll
        for (int k = 0; k < 8; ++k)
            acc[k] += __shfl_xor_sync(0xffffffffu, acc[k], m);
    }
    const int warp = tid >> 5;
    const int lane = tid & 31;
    if (lane < 2) {
        #pragma unroll
        for (int k = 0; k < 8; ++k) red2[warp][lane][k] = acc[k];
    }
    __syncthreads();
    float r = 0.f;
    if (tid < NCOL) {
        const int cj = tid >> 3;
        const int ck = tid & 7;
        #pragma unroll
        for (int w = 0; w < 16; ++w)
            r += red2[w][cj][ck];
    }
    return r;
}

// ---------------------------------------------------------------------------
// Streamed layer: chunks 0..3 in flight on entry; issues its remaining
// chunks then next STREAMED layer's chunks 0..3. Input x-values are loaded
// DIRECTLY into registers right after the barrier (no smem staging / STS
// drain on the critical path); each thread needs 2 values per chunk.
// Result valid for tid<16.
// ---------------------------------------------------------------------------
__device__ __forceinline__ float stream_layer(
    const char* __restrict__ slice,  int K,  bool act,
    const char* __restrict__ slicen, int Kn, bool actn,
    const float* __restrict__ in,
    char* __restrict__ bufs,
    int& is, int& rs, float (*red2)[2][8],
    int tid, unsigned& nbar)
{
    grid_barrier(nbar);

    const int kw = tid >> 1;          // 0..255
    const int jv = tid & 1;
    const int nc = (K + CHUNK - 1) / CHUNK;   // 4 (HID) or 5 (KIN)

    // Register-direct input loads (independent; overlap cp.async waits).
    float xv[10];
    #pragma unroll
    for (int c = 0; c < 5; ++c) {
        if (c < nc) {
            const int r0 = c*CHUNK + kw;
            const int r1 = c*CHUNK + 256 + kw;
            xv[2*c]   = (r0 < K) ? __ldcg(in + r0) : 0.f;
            xv[2*c+1] = (r1 < K) ? __ldcg(in + r1) : 0.f;
        }
    }

    float acc[8];
    #pragma unroll
    for (int k = 0; k < 8; ++k) acc[k] = 0.f;

    for (int c = 0; c < nc; ++c) {
        asm volatile("cp.async.wait_group 3;");   // chunk c landed
        __syncthreads();                          // chunk c-1 reads done

        if (c < nc - LOOKAHEAD)
            prefetch_chunk(slice,  K,  (c + LOOKAHEAD)*CHUNK,
                           bufs + is*BUF_BYTES, tid, act);
        else
            prefetch_chunk(slicen, Kn, (c - (nc - LOOKAHEAD))*CHUNK,
                           bufs + is*BUF_BYTES, tid, actn);
        if (++is == NBUF) is = 0;

        if (act) {
            const char* __restrict__ buf = bufs + rs*BUF_BYTES;
            const int base = c * CHUNK;
            const int rows = min(CHUNK, K - base);
            if (kw < rows)
                mac8(acc, buf + kw*32, jv, xv[2*c]);
            if (kw + 256 < rows)
                mac8(acc, buf + (kw + 256)*32, jv, xv[2*c+1]);
        }
        if (++rs == NBUF) rs = 0;
    }
    return reduce_tail(acc, red2, tid);
}

// ---------------------------------------------------------------------------
// Resident layer: weights live permanently in SMEM; input x-values loaded
// directly into registers. No chunk machinery, no staging sync at all.
// ---------------------------------------------------------------------------
__device__ __forceinline__ float resident_layer(
    const char* __restrict__ wres,
    const float* __restrict__ in,
    float (*red2)[2][8],
    int tid, unsigned& nbar)
{
    grid_barrier(nbar);

    const int kw = tid >> 1;
    const int jv = tid & 1;

    float xv[8];
    #pragma unroll
    for (int i = 0; i < 8; ++i)
        xv[i] = __ldcg(in + kw + i*256);          // HID = 2048, no guards

    float acc[8];
    #pragma unroll
    for (int k = 0; k < 8; ++k) acc[k] = 0.f;

    #pragma unroll
    for (int i = 0; i < 8; ++i)
        mac8(acc, wres + (kw + i*256)*32, jv, xv[i]);

    return reduce_tail(acc, red2, tid);
}

__device__ __forceinline__ void store_hidden(float r,
        const float* __restrict__ bias, float* __restrict__ out,
        int j0, int tid)
{
    if (tid < NCOL) {
        const int j = j0 + tid;
        out[j] = fmaxf(r + __ldg(bias + j), 0.f);
    }
}

// ---------------------------------------------------------------------------
// Setup kernel: weight reorg (y = 0..5) + barrier/x0/te init (y = 6), fused
// so the bridge kernel is the 2nd launch per replay (ncu sampling hits it).
// ---------------------------------------------------------------------------
__global__ void setup_kernel(
    const float* __restrict__ w0, const float* __restrict__ w1,
    const float* __restrict__ w2, const float* __restrict__ w3,
    const float* __restrict__ w4, const float* __restrict__ wout,
    const float* __restrict__ start,
    const float* __restrict__ te_w1, const float* __restrict__ te_b1,
    const float* __restrict__ te_w2, const float* __restrict__ te_b2,
    float* __restrict__ out)
{
    const int b = blockIdx.x;   // 0..127
    const int l = blockIdx.y;   // 0..6

    if (l < 6) {                // ---- weight reorg ----
        const float* W; int K, O; long off;
        switch (l) {
            case 0: W = w0;   K = KIN; O = HID;  off = OFF0; break;
            case 1: W = w1;   K = HID; O = HID;  off = OFF1; break;
            case 2: W = w2;   K = HID; O = HID;  off = OFF2; break;
            case 3: W = w3;   K = HID; O = HID;  off = OFF3; break;
            case 4: W = w4;   K = HID; O = HID;  off = OFF4; break;
            default:W = wout; K = HID; O = GENE; off = OFFO; break;
        }
        const int j0 = b * NCOL;
        if (j0 >= O) return;
        __nv_bfloat16* dst = g_wrep + off + (long)b * K * NCOL;
        const int n4 = K * (NCOL/4);
        for (int e = threadIdx.x; e < n4; e += blockDim.x) {
            const int r  = e >> 2;
            const int c4 = (e & 3) * 4;
            const float4 w = *reinterpret_cast<const float4*>(W + (long)r * O + j0 + c4);
            uint2 p;
            __nv_bfloat162 p0 = __float22bfloat162_rn(make_float2(w.x, w.y));
            __nv_bfloat162 p1 = __float22bfloat162_rn(make_float2(w.z, w.w));
            p.x = *reinterpret_cast<unsigned*>(&p0);
            p.y = *reinterpret_cast<unsigned*>(&p1);
            *reinterpret_cast<uint2*>(dst + (long)e * 4) = p;
        }
    } else {                    // ---- init: t = 2b and 2b+1 ----
        __shared__ float h[2][TE];
        const int half = threadIdx.x >> 7;       // 0 or 1
        const int lane = threadIdx.x & 127;
        const int t    = 2*b + half;
        const float tt = (float)t * DT;
        h[half][lane] = fmaxf(fmaf(tt, te_w1[lane], te_b1[lane]), 0.f);
        __syncthreads();
        float acc = te_b2[lane];
        #pragma unroll 8
        for (int k = 0; k < TE; ++k)
            acc = fmaf(h[half][k], te_w2[k * TE + lane], acc);
        if (t >= 1) {
            g_te[t][lane] = acc;
            if (t == 1) g_x[0][GENE + lane] = acc;   // te(1) tail for step 1
        } else {                // t == 0: barrier reset + x0 seed + row 0
            if (lane == 0) g_count = 0u;
            for (int k = lane; k < GENE; k += TE) {
                const float v = start[k];
                g_x[0][k] = v;
                out[k]    = v;
            }
        }
    }
}

// ---------------------------------------------------------------------------
// Persistent kernel: 255 Euler steps, 6 flat barriers/step. Layers 1-2 from
// SMEM-resident slabs; layers 0,3,4,out stream via depth-5 cp.async with
// 4-chunk cross-layer lookahead. Inputs register-loaded (no smem staging).
// ---------------------------------------------------------------------------
__global__ void __launch_bounds__(BLOCK, 1) bridge_kernel(
    const float* __restrict__ b0, const float* __restrict__ b1,
    const float* __restrict__ b2, const float* __restrict__ b3,
    const float* __restrict__ b4, const float* __restrict__ bout,
    float* __restrict__ out)
{
    extern __shared__ float smem[];
    char*  bufs = reinterpret_cast<char*>(smem);
    char*  rw1  = bufs + NBUF*BUF_BYTES;                // resident w1 slab
    char*  rw2  = rw1 + SLAB_BYTES;                     // resident w2 slab
    __shared__ float red2[16][2][8];

    const int tid = threadIdx.x;
    const int b   = blockIdx.x;
    const int j0  = b * NCOL;
    const bool actO = (j0 < GENE);      // active in the output layer

    const char* s0 = reinterpret_cast<const char*>(g_wrep + OFF0 + (long)b * KIN * NCOL);
    const char* s1 = reinterpret_cast<const char*>(g_wrep + OFF1 + (long)b * HID * NCOL);
    const char* s2 = reinterpret_cast<const char*>(g_wrep + OFF2 + (long)b * HID * NCOL);
    const char* s3 = reinterpret_cast<const char*>(g_wrep + OFF3 + (long)b * HID * NCOL);
    const char* s4 = reinterpret_cast<const char*>(g_wrep + OFF4 + (long)b * HID * NCOL);
    const char* so = reinterpret_cast<const char*>(g_wrep + OFFO + (long)b * HID * NCOL);

    unsigned nbar = 0;
    int is = 0, rs = 0;

    // Prologue: resident slabs (one cp.async group, drains at first wait),
    // then chunks 0..3 of step-1 layer0.
    for (int i = tid; i < SLAB_BYTES/16; i += BLOCK) cp16(rw1 + i*16, s1 + (long)i*16);
    for (int i = tid; i < SLAB_BYTES/16; i += BLOCK) cp16(rw2 + i*16, s2 + (long)i*16);
    asm volatile("cp.async.commit_group;");
    #pragma unroll
    for (int c = 0; c < LOOKAHEAD; ++c)
        prefetch_chunk(s0, KIN, c*CHUNK, bufs + c*BUF_BYTES, tid, true);
    is = LOOKAHEAD;

    for (int t = 1; t < NSTEP; ++t) {
        const float* xprev = g_x[(t - 1) & 1];
        float*       xcur  = g_x[t & 1];
        float r;

        r = stream_layer(s0, KIN, true,  s3, HID, true,  xprev,
                         bufs, is, rs, red2, tid, nbar);
        store_hidden(r, b0, g_h0, j0, tid);

        r = resident_layer(rw1, g_h0, red2, tid, nbar);
        store_hidden(r, b1, g_h1, j0, tid);

        r = resident_layer(rw2, g_h1, red2, tid, nbar);
        store_hidden(r, b2, g_h0, j0, tid);

        r = stream_layer(s3, HID, true,  s4, HID, true,  g_h0,
                         bufs, is, rs, red2, tid, nbar);
        store_hidden(r, b3, g_h1, j0, tid);

        r = stream_layer(s4, HID, true,  so, HID, actO,  g_h1,
                         bufs, is, rs, red2, tid, nbar);
        store_hidden(r, b4, g_h0, j0, tid);

        // Final layer + Euler update + trajectory store
        r = stream_layer(so, HID, actO,  s0, KIN, true,  g_h0,
                         bufs, is, rs, red2, tid, nbar);
        if (tid < NCOL && actO) {
            const int j = j0 + tid;
            const float xn = fmaf(r + __ldg(bout + j), DT, __ldcg(xprev + j));
            xcur[j] = xn;
            __stcs(out + (size_t)t * GENE + j, xn);
        }
        // tail CTA installs te(t+1) into xcur tail for next step's layer0
        if (b == GRID - 1 && t + 1 < NSTEP && tid < TE)
            xcur[GENE + tid] = g_te[t + 1][tid];
    }
}

extern "C" void kernel_launch(void* const* d_in, const int* in_sizes, int n_in,
                              void* d_out, int out_size)
{
    (void)in_sizes; (void)n_in; (void)out_size;
    const float* start  = (const float*)d_in[0];
    // d_in[1] = end_state (unused)
    const float* te_w1  = (const float*)d_in[2];
    const float* te_b1  = (const float*)d_in[3];
    const float* te_w2  = (const float*)d_in[4];
    const float* te_b2  = (const float*)d_in[5];
    const float* w0     = (const float*)d_in[6];
    const float* b0     = (const float*)d_in[7];
    const float* w1     = (const float*)d_in[8];
    const float* b1     = (const float*)d_in[9];
    const float* w2     = (const float*)d_in[10];
    const float* b2     = (const float*)d_in[11];
    const float* w3     = (const float*)d_in[12];
    const float* b3     = (const float*)d_in[13];
    const float* w4     = (const float*)d_in[14];
    const float* b4     = (const float*)d_in[15];
    const float* wout   = (const float*)d_in[16];
    const float* bout   = (const float*)d_in[17];
    float* out = (float*)d_out;

    cudaFuncSetAttribute(bridge_kernel,
                         cudaFuncAttributeMaxDynamicSharedMemorySize, SMEM_BYTES);

    dim3 sg(GRID, 7);
    setup_kernel<<<sg, 256>>>(w0, w1, w2, w3, w4, wout,
                              start, te_w1, te_b1, te_w2, te_b2, out);
    bridge_kernel<<<GRID, BLOCK, SMEM_BYTES>>>(b0, b1, b2, b3, b4, bout, out);
}

// round 16
// speedup vs baseline: 1.2214x; 1.0411x over previous
#include <cuda_runtime.h>
#include <cuda_bf16.h>
#include <cstdint>

#define GENE   2000
#define TE     128
#define HID    2048
#define KIN    2128      // GENE + TE (time embedding lives in x tail)
#define NSTEP  256
#define GRID   128
#define BLOCK  512
#define NCOL   16        // output columns per CTA
#define DT     (1.0f/255.0f)
#define SLAB_BYTES (HID*NCOL*2)             // 64 KB resident slab per layer
#define SMEM_BYTES (2*SLAB_BYTES)           // 128 KB (slabs only; no stream bufs)

// Permuted bf16 weights: per-CTA slice contiguous.
#define OFF0   0L
#define OFF1   (OFF0 + 128L*KIN*NCOL)
#define OFF2   (OFF1 + 128L*HID*NCOL)
#define OFF3   (OFF2 + 128L*HID*NCOL)
#define OFF4   (OFF3 + 128L*HID*NCOL)
#define OFFO   (OFF4 + 128L*HID*NCOL)
#define TOTALF (OFFO + 125L*HID*NCOL)       // ~25.2M bf16 = ~48 MB (L2-resident)

// Persistent scratch (device globals: allocation is forbidden)
__device__ __nv_bfloat16 g_wrep[TOTALF];
__device__ float    g_x[2][2176];      // x ping-pong: [0,2000)=x, [2000,2128)=te(t)
__device__ float    g_h0[HID];
__device__ float    g_h1[HID];
__device__ float    g_te[NSTEP][TE];
__device__ unsigned g_count;           // flat barrier counter (red-based)

// ---------------------------------------------------------------------------
// Grid barrier: FLAT monotonic counter (red.release arrival, acquire poll).
// ---------------------------------------------------------------------------
__device__ __forceinline__ void grid_barrier(unsigned& nbar) {
    __syncthreads();
    ++nbar;
    if (threadIdx.x == 0) {
        asm volatile("red.release.gpu.add.u32 [%0], 1;" :: "l"(&g_count) : "memory");
        const unsigned target = nbar * GRID;
        unsigned cur;
        do {
            asm volatile("ld.acquire.gpu.u32 %0, [%1];" : "=r"(cur) : "l"(&g_count) : "memory");
        } while (cur < target);
    }
    __syncthreads();
}

// 8-col MAC on one 32-byte weight row held in a register uint4.
__device__ __forceinline__ void mac8u(float* acc, uint4 wv, float xv) {
    const float2 f0 = __bfloat1622float2(*reinterpret_cast<const __nv_bfloat162*>(&wv.x));
    const float2 f1 = __bfloat1622float2(*reinterpret_cast<const __nv_bfloat162*>(&wv.y));
    const float2 f2 = __bfloat1622float2(*reinterpret_cast<const __nv_bfloat162*>(&wv.z));
    const float2 f3 = __bfloat1622float2(*reinterpret_cast<const __nv_bfloat162*>(&wv.w));
    acc[0] = fmaf(xv, f0.x, acc[0]);
    acc[1] = fmaf(xv, f0.y, acc[1]);
    acc[2] = fmaf(xv, f1.x, acc[2]);
    acc[3] = fmaf(xv, f1.y, acc[3]);
    acc[4] = fmaf(xv, f2.x, acc[4]);
    acc[5] = fmaf(xv, f2.y, acc[5]);
    acc[6] = fmaf(xv, f3.x, acc[6]);
    acc[7] = fmaf(xv, f3.y, acc[7]);
}

// Same MAC reading the row from an SMEM-resident slab.
__device__ __forceinline__ void mac8s(float* acc, const char* rowp, int jv, float xv) {
    const uint4 wv = *reinterpret_cast<const uint4*>(rowp + jv*16);
    mac8u(acc, wv, xv);
}

// Load one layer's per-thread weight rows (uint4 each) into registers.
// NROWN = 8 for K=HID (no guard), 9 for K=KIN (last row guarded).
template<int NROWN>
__device__ __forceinline__ void load_w(uint4* wv, const char* slice, int K,
                                       int kw, int jv, bool act) {
    if (act) {
        #pragma unroll
        for (int i = 0; i < NROWN; ++i) {
            const int r = kw + i*256;
            if (NROWN == 8 || r < K)
                wv[i] = __ldg(reinterpret_cast<const uint4*>(slice + (long)r*32 + jv*16));
        }
    }
}

// Cross-thread reduction of 8-col accumulators over 16 warps. Returns the
// column sum for tid<16 (col j0+tid).
__device__ __forceinline__ float reduce_tail(float* acc, float (*red2)[2][8], int tid) {
    #pragma unroll
    for (int m = 2; m <= 16; m <<= 1) {
        #pragma unroll
        for (int k = 0; k < 8; ++k)
            acc[k] += __shfl_xor_sync(0xffffffffu, acc[k], m);
    }
    const int warp = tid >> 5;
    const int lane = tid & 31;
    if (lane < 2) {
        #pragma unroll
        for (int k = 0; k < 8; ++k) red2[warp][lane][k] = acc[k];
    }
    __syncthreads();
    float r = 0.f;
    if (tid < NCOL) {
        const int cj = tid >> 3;
        const int ck = tid & 7;
        #pragma unroll
        for (int w = 0; w < 16; ++w)
            r += red2[w][cj][ck];
    }
    return r;
}

// ---------------------------------------------------------------------------
// Register-weight layer. wv holds THIS layer's weights on entry (loaded
// before the previous barrier). After consuming them, issues the NEXT
// register layer's weight loads into the same registers — they complete
// during the reduce tail / barrier wait / intervening resident layers.
// Post-barrier exposed latency = the x loads only. Result valid for tid<16.
// ---------------------------------------------------------------------------
template<int NROW, int NROWN>
__device__ __forceinline__ float reg_layer(
    uint4* wv, const float* __restrict__ in, int K, bool act,
    const char* __restrict__ slicen, int Kn, bool actn,
    float (*red2)[2][8], int tid, unsigned& nbar)
{
    grid_barrier(nbar);

    const int kw = tid >> 1;
    const int jv = tid & 1;

    float xv[NROW];
    #pragma unroll
    for (int i = 0; i < NROW; ++i) {
        const int r = kw + i*256;
        xv[i] = (NROW == 8 || r < K) ? __ldcg(in + r) : 0.f;
    }

    float acc[8];
    #pragma unroll
    for (int k = 0; k < 8; ++k) acc[k] = 0.f;

    if (act) {
        #pragma unroll
        for (int i = 0; i < NROW; ++i) {
            const int r = kw + i*256;
            if (NROW == 8 || r < K)
                mac8u(acc, wv[i], xv[i]);
        }
    }

    // Prefetch next register-layer's weights (regs now reusable).
    load_w<NROWN>(wv, slicen, Kn, kw, jv, actn);

    return reduce_tail(acc, red2, tid);
}

// ---------------------------------------------------------------------------
// Resident layer: weights live permanently in SMEM; x register-loaded.
// ---------------------------------------------------------------------------
__device__ __forceinline__ float resident_layer(
    const char* __restrict__ wres,
    const float* __restrict__ in,
    float (*red2)[2][8],
    int tid, unsigned& nbar)
{
    grid_barrier(nbar);

    const int kw = tid >> 1;
    const int jv = tid & 1;

    float xv[8];
    #pragma unroll
    for (int i = 0; i < 8; ++i)
        xv[i] = __ldcg(in + kw + i*256);

    float acc[8];
    #pragma unroll
    for (int k = 0; k < 8; ++k) acc[k] = 0.f;

    #pragma unroll
    for (int i = 0; i < 8; ++i)
        mac8s(acc, wres + (long)(kw + i*256)*32, jv, xv[i]);

    return reduce_tail(acc, red2, tid);
}

__device__ __forceinline__ void store_hidden(float r,
        const float* __restrict__ bias, float* __restrict__ out,
        int j0, int tid)
{
    if (tid < NCOL) {
        const int j = j0 + tid;
        out[j] = fmaxf(r + __ldg(bias + j), 0.f);
    }
}

// ---------------------------------------------------------------------------
// Setup kernel: weight reorg (y = 0..5) + barrier/x0/te init (y = 6), fused
// so the bridge kernel is the 2nd launch per replay (ncu sampling hits it).
// ---------------------------------------------------------------------------
__global__ void setup_kernel(
    const float* __restrict__ w0, const float* __restrict__ w1,
    const float* __restrict__ w2, const float* __restrict__ w3,
    const float* __restrict__ w4, const float* __restrict__ wout,
    const float* __restrict__ start,
    const float* __restrict__ te_w1, const float* __restrict__ te_b1,
    const float* __restrict__ te_w2, const float* __restrict__ te_b2,
    float* __restrict__ out)
{
    const int b = blockIdx.x;   // 0..127
    const int l = blockIdx.y;   // 0..6

    if (l < 6) {                // ---- weight reorg ----
        const float* W; int K, O; long off;
        switch (l) {
            case 0: W = w0;   K = KIN; O = HID;  off = OFF0; break;
            case 1: W = w1;   K = HID; O = HID;  off = OFF1; break;
            case 2: W = w2;   K = HID; O = HID;  off = OFF2; break;
            case 3: W = w3;   K = HID; O = HID;  off = OFF3; break;
            case 4: W = w4;   K = HID; O = HID;  off = OFF4; break;
            default:W = wout; K = HID; O = GENE; off = OFFO; break;
        }
        const int j0 = b * NCOL;
        if (j0 >= O) return;
        __nv_bfloat16* dst = g_wrep + off + (long)b * K * NCOL;
        const int n4 = K * (NCOL/4);
        for (int e = threadIdx.x; e < n4; e += blockDim.x) {
            const int r  = e >> 2;
            const int c4 = (e & 3) * 4;
            const float4 w = *reinterpret_cast<const float4*>(W + (long)r * O + j0 + c4);
            uint2 p;
            __nv_bfloat162 p0 = __float22bfloat162_rn(make_float2(w.x, w.y));
            __nv_bfloat162 p1 = __float22bfloat162_rn(make_float2(w.z, w.w));
            p.x = *reinterpret_cast<unsigned*>(&p0);
            p.y = *reinterpret_cast<unsigned*>(&p1);
            *reinterpret_cast<uint2*>(dst + (long)e * 4) = p;
        }
    } else {                    // ---- init: t = 2b and 2b+1 ----
        __shared__ float h[2][TE];
        const int half = threadIdx.x >> 7;       // 0 or 1
        const int lane = threadIdx.x & 127;
        const int t    = 2*b + half;
        const float tt = (float)t * DT;
        h[half][lane] = fmaxf(fmaf(tt, te_w1[lane], te_b1[lane]), 0.f);
        __syncthreads();
        float acc = te_b2[lane];
        #pragma unroll 8
        for (int k = 0; k < TE; ++k)
            acc = fmaf(h[half][k], te_w2[k * TE + lane], acc);
        if (t >= 1) {
            g_te[t][lane] = acc;
            if (t == 1) g_x[0][GENE + lane] = acc;   // te(1) tail for step 1
        } else {                // t == 0: barrier reset + x0 seed + row 0
            if (lane == 0) g_count = 0u;
            for (int k = lane; k < GENE; k += TE) {
                const float v = start[k];
                g_x[0][k] = v;
                out[k]    = v;
            }
        }
    }
}

// ---------------------------------------------------------------------------
// Persistent kernel: 255 Euler steps, 6 flat barriers/step. Layers 1-2 from
// SMEM-resident slabs; layers 0,3,4,out run with REGISTER-resident weights
// loaded directly from L2 (all weights L2-resident, measured DRAM=0.1%),
// with cross-barrier register prefetch. No cp.async, no per-chunk syncs.
// ---------------------------------------------------------------------------
__global__ void __launch_bounds__(BLOCK, 1) bridge_kernel(
    const float* __restrict__ b0, const float* __restrict__ b1,
    const float* __restrict__ b2, const float* __restrict__ b3,
    const float* __restrict__ b4, const float* __restrict__ bout,
    float* __restrict__ out)
{
    extern __shared__ float smem[];
    char* rw1 = reinterpret_cast<char*>(smem);          // resident w1 slab
    char* rw2 = rw1 + SLAB_BYTES;                       // resident w2 slab
    __shared__ float red2[16][2][8];

    const int tid = threadIdx.x;
    const int b   = blockIdx.x;
    const int j0  = b * NCOL;
    const bool actO = (j0 < GENE);      // active in the output layer
    const int kw = tid >> 1;
    const int jv = tid & 1;

    const char* s0 = reinterpret_cast<const char*>(g_wrep + OFF0 + (long)b * KIN * NCOL);
    const char* s1 = reinterpret_cast<const char*>(g_wrep + OFF1 + (long)b * HID * NCOL);
    const char* s2 = reinterpret_cast<const char*>(g_wrep + OFF2 + (long)b * HID * NCOL);
    const char* s3 = reinterpret_cast<const char*>(g_wrep + OFF3 + (long)b * HID * NCOL);
    const char* s4 = reinterpret_cast<const char*>(g_wrep + OFF4 + (long)b * HID * NCOL);
    const char* so = reinterpret_cast<const char*>(g_wrep + OFFO + (long)b * HID * NCOL);

    unsigned nbar = 0;

    // Prologue: resident slabs into smem (ordered before first use by the
    // STS-draining __syncthreads inside the first grid_barrier), and layer0
    // weights into registers.
    for (int i = tid; i < SLAB_BYTES/16; i += BLOCK)
        *reinterpret_cast<uint4*>(rw1 + i*16) =
            __ldg(reinterpret_cast<const uint4*>(s1 + (long)i*16));
    for (int i = tid; i < SLAB_BYTES/16; i += BLOCK)
        *reinterpret_cast<uint4*>(rw2 + i*16) =
            __ldg(reinterpret_cast<const uint4*>(s2 + (long)i*16));

    uint4 wv[9];
    load_w<9>(wv, s0, KIN, kw, jv, true);

    for (int t = 1; t < NSTEP; ++t) {
        const float* xprev = g_x[(t - 1) & 1];
        float*       xcur  = g_x[t & 1];
        float r;

        // Layer 0 (consume s0, prefetch s3 — has 2 resident layers to land)
        r = reg_layer<9,8>(wv, xprev, KIN, true,  s3, HID, true,
                           red2, tid, nbar);
        store_hidden(r, b0, g_h0, j0, tid);

        r = resident_layer(rw1, g_h0, red2, tid, nbar);
        store_hidden(r, b1, g_h1, j0, tid);

        r = resident_layer(rw2, g_h1, red2, tid, nbar);
        store_hidden(r, b2, g_h0, j0, tid);

        // Layer 3 (consume s3, prefetch s4)
        r = reg_layer<8,8>(wv, g_h0, HID, true,  s4, HID, true,
                           red2, tid, nbar);
        store_hidden(r, b3, g_h1, j0, tid);

        // Layer 4 (consume s4, prefetch so)
        r = reg_layer<8,8>(wv, g_h1, HID, true,  so, HID, actO,
                           red2, tid, nbar);
        store_hidden(r, b4, g_h0, j0, tid);

        // Output layer (consume so, prefetch s0 for the next step)
        r = reg_layer<8,9>(wv, g_h0, HID, actO,  s0, KIN, true,
                           red2, tid, nbar);
        if (tid < NCOL && actO) {
            const int j = j0 + tid;
            const float xn = fmaf(r + __ldg(bout + j), DT, __ldcg(xprev + j));
            xcur[j] = xn;
            __stcs(out + (size_t)t * GENE + j, xn);
        }
        // tail CTA installs te(t+1) into xcur tail for next step's layer0
        if (b == GRID - 1 && t + 1 < NSTEP && tid < TE)
            xcur[GENE + tid] = g_te[t + 1][tid];
    }
}

extern "C" void kernel_launch(void* const* d_in, const int* in_sizes, int n_in,
                              void* d_out, int out_size)
{
    (void)in_sizes; (void)n_in; (void)out_size;
    const float* start  = (const float*)d_in[0];
    // d_in[1] = end_state (unused)
    const float* te_w1  = (const float*)d_in[2];
    const float* te_b1  = (const float*)d_in[3];
    const float* te_w2  = (const float*)d_in[4];
    const float* te_b2  = (const float*)d_in[5];
    const float* w0     = (const float*)d_in[6];
    const float* b0     = (const float*)d_in[7];
    const float* w1     = (const float*)d_in[8];
    const float* b1     = (const float*)d_in[9];
    const float* w2     = (const float*)d_in[10];
    const float* b2     = (const float*)d_in[11];
    const float* w3     = (const float*)d_in[12];
    const float* b3     = (const float*)d_in[13];
    const float* w4     = (const float*)d_in[14];
    const float* b4     = (const float*)d_in[15];
    const float* wout   = (const float*)d_in[16];
    const float* bout   = (const float*)d_in[17];
    float* out = (float*)d_out;

    cudaFuncSetAttribute(bridge_kernel,
                         cudaFuncAttributeMaxDynamicSharedMemorySize, SMEM_BYTES);

    dim3 sg(GRID, 7);
    setup_kernel<<<sg, 256>>>(w0, w1, w2, w3, w4, wout,
                              start, te_w1, te_b1, te_w2, te_b2, out);
    bridge_kernel<<<GRID, BLOCK, SMEM_BYTES>>>(b0, b1, b2, b3, b4, bout, out);
}